// round 15
// baseline (speedup 1.0000x reference)
#include <cuda_runtime.h>
#include <cstdint>

// Problem constants (shapes fixed by the dataset)
#define NN    4096          // nodes
#define IND   256           // feature dim
#define EDIM  16            // edge feature dim
#define NAF   16            // atom features
#define LATD  128           // latent dim
#define NBT   5             // bond types
#define EMAX  262144        // edges

#define LAT_OFF   0
#define ATOM_OFF  (NN * LATD)              // 524288
#define BOND_OFF  (NN * LATD + NN * NAF)   // 589824

// Device scratch (allocation-free per harness rules)
__device__ float g_s1[NN * IND];           // 4 MB: silu(s@Wsharedᵀ+b)
__device__ float g_esym[EMAX * EDIM];      // 16 MB: symmetrized edge features
__device__ int   g_map[NN * NN];           // 64 MB: (j,i) -> winning edge k+1 (zero-invariant)

// ---------- packed f32x2 helpers (Blackwell FFMA2 path) ----------
static __device__ __forceinline__ unsigned long long pk2(float lo, float hi) {
    unsigned long long r;
    asm("mov.b64 %0, {%1, %2};" : "=l"(r) : "f"(lo), "f"(hi));
    return r;
}
static __device__ __forceinline__ unsigned long long dup2(float v) {
    unsigned long long r;
    asm("mov.b64 %0, {%1, %1};" : "=l"(r) : "f"(v));
    return r;
}
static __device__ __forceinline__ void up2(float &lo, float &hi, unsigned long long v) {
    asm("mov.b64 {%0, %1}, %2;" : "=f"(lo), "=f"(hi) : "l"(v));
}
static __device__ __forceinline__ void fma2(unsigned long long &d,
                                            unsigned long long a,
                                            unsigned long long b) {
    asm("fma.rn.f32x2 %0, %1, %2, %0;" : "+l"(d) : "l"(a), "l"(b));
}
static __device__ __forceinline__ unsigned long long add2(unsigned long long a,
                                                          unsigned long long b) {
    unsigned long long r;
    asm("add.rn.f32x2 %0, %1, %2;" : "=l"(r) : "l"(a), "l"(b));
    return r;
}
static __device__ __forceinline__ float silu_f(float x) {
    // x * sigmoid(x) = x / (1 + e^-x); MUFU EX2 + MUFU RCP fast path
    return __fdividef(x, 1.0f + __expf(-x));
}

// ---------- K1: s1 = silu(s @ W_sharedᵀ + b_shared)  [4096,256]x[256,256] ----------
__global__ __launch_bounds__(256) void k_gemm_silu(
    const float* __restrict__ A, const float* __restrict__ W,
    const float* __restrict__ bias)
{
    __shared__ float As[32][132];
    __shared__ float Bs[32][68];
    const int tid = threadIdx.x;
    const int bm = blockIdx.y * 128, bn = blockIdx.x * 64;
    const int tx = tid & 15, ty = tid >> 4;

    float acc[8][4];
    #pragma unroll
    for (int i = 0; i < 8; i++)
        #pragma unroll
        for (int j = 0; j < 4; j++) acc[i][j] = 0.f;

    for (int kk = 0; kk < 256; kk += 32) {
        #pragma unroll
        for (int l = 0; l < 4; l++) {
            int idx = tid + l * 256;           // 1024 float4s of the 128x32 A tile
            int m = idx >> 3, kg = idx & 7;
            float4 v = *(const float4*)&A[(bm + m) * 256 + kk + kg * 4];
            As[kg * 4 + 0][m] = v.x; As[kg * 4 + 1][m] = v.y;
            As[kg * 4 + 2][m] = v.z; As[kg * 4 + 3][m] = v.w;
        }
        #pragma unroll
        for (int l = 0; l < 2; l++) {
            int idx = tid + l * 256;           // 512 float4s of the 64x32 W tile
            int c = idx >> 3, kg = idx & 7;
            float4 v = *(const float4*)&W[(bn + c) * 256 + kk + kg * 4];
            Bs[kg * 4 + 0][c] = v.x; Bs[kg * 4 + 1][c] = v.y;
            Bs[kg * 4 + 2][c] = v.z; Bs[kg * 4 + 3][c] = v.w;
        }
        __syncthreads();
        #pragma unroll
        for (int k = 0; k < 32; k++) {
            float4 a0 = *(const float4*)&As[k][ty * 8];
            float4 a1 = *(const float4*)&As[k][ty * 8 + 4];
            float4 b  = *(const float4*)&Bs[k][tx * 4];
            float aa[8] = {a0.x, a0.y, a0.z, a0.w, a1.x, a1.y, a1.z, a1.w};
            float bb[4] = {b.x, b.y, b.z, b.w};
            #pragma unroll
            for (int i = 0; i < 8; i++)
                #pragma unroll
                for (int j = 0; j < 4; j++)
                    acc[i][j] = fmaf(aa[i], bb[j], acc[i][j]);
        }
        __syncthreads();
    }
    float4 b4 = *(const float4*)&bias[bn + tx * 4];
    const float bv[4] = {b4.x, b4.y, b4.z, b4.w};
    #pragma unroll
    for (int i = 0; i < 8; i++) {
        int row = bm + ty * 8 + i;
        float4 o;
        o.x = silu_f(acc[i][0] + bv[0]);
        o.y = silu_f(acc[i][1] + bv[1]);
        o.z = silu_f(acc[i][2] + bv[2]);
        o.w = silu_f(acc[i][3] + bv[3]);
        *(float4*)&g_s1[row * 256 + bn + tx * 4] = o;
    }
}

// ---------- K2: atoms_out = s1 @ W_atomsᵀ + b_atoms ; split into latent/atoms ----------
__global__ __launch_bounds__(256) void k_gemm_atoms(
    const float* __restrict__ W, const float* __restrict__ bias,
    float* __restrict__ out)
{
    __shared__ float As[32][132];
    __shared__ float Bs[32][52];
    const int tid = threadIdx.x;
    const int bm = blockIdx.y * 128, bn = blockIdx.x * 48;
    const int tx = tid & 15, ty = tid >> 4;

    float acc[8][3];
    #pragma unroll
    for (int i = 0; i < 8; i++)
        #pragma unroll
        for (int j = 0; j < 3; j++) acc[i][j] = 0.f;

    for (int kk = 0; kk < 256; kk += 32) {
        #pragma unroll
        for (int l = 0; l < 4; l++) {
            int idx = tid + l * 256;
            int m = idx >> 3, kg = idx & 7;
            float4 v = *(const float4*)&g_s1[(bm + m) * 256 + kk + kg * 4];
            As[kg * 4 + 0][m] = v.x; As[kg * 4 + 1][m] = v.y;
            As[kg * 4 + 2][m] = v.z; As[kg * 4 + 3][m] = v.w;
        }
        #pragma unroll
        for (int l = 0; l < 2; l++) {
            int idx = tid + l * 256;           // 384 float4s of the 48x32 W tile
            if (idx < 384) {
                int c = idx >> 3, kg = idx & 7;
                float4 v = *(const float4*)&W[(bn + c) * 256 + kk + kg * 4];
                Bs[kg * 4 + 0][c] = v.x; Bs[kg * 4 + 1][c] = v.y;
                Bs[kg * 4 + 2][c] = v.z; Bs[kg * 4 + 3][c] = v.w;
            }
        }
        __syncthreads();
        #pragma unroll
        for (int k = 0; k < 32; k++) {
            float4 a0 = *(const float4*)&As[k][ty * 8];
            float4 a1 = *(const float4*)&As[k][ty * 8 + 4];
            float aa[8] = {a0.x, a0.y, a0.z, a0.w, a1.x, a1.y, a1.z, a1.w};
            float b0 = Bs[k][tx * 3 + 0];
            float b1 = Bs[k][tx * 3 + 1];
            float b2 = Bs[k][tx * 3 + 2];
            #pragma unroll
            for (int i = 0; i < 8; i++) {
                acc[i][0] = fmaf(aa[i], b0, acc[i][0]);
                acc[i][1] = fmaf(aa[i], b1, acc[i][1]);
                acc[i][2] = fmaf(aa[i], b2, acc[i][2]);
            }
        }
        __syncthreads();
    }
    #pragma unroll
    for (int i = 0; i < 8; i++) {
        int row = bm + ty * 8 + i;
        #pragma unroll
        for (int j = 0; j < 3; j++) {
            int col = bn + tx * 3 + j;
            if (col < NAF + LATD) {
                float val = acc[i][j] + bias[col];
                if (col < NAF)
                    out[ATOM_OFF + row * NAF + col] = val;        // atoms_pred
                else
                    out[LAT_OFF + row * LATD + (col - NAF)] = val; // latent_pred
            }
        }
    }
}

// ---------- K3: scatter last-write-wins map (edge_index is int32: JAX demotes int64) ----------
__global__ void k_scatter(const int* __restrict__ ei, int E)
{
    int k = blockIdx.x * blockDim.x + threadIdx.x;
    if (k >= E) return;
    int j = ei[k]     & (NN - 1);
    int i = ei[E + k] & (NN - 1);
    atomicMax(&g_map[j * NN + i], k + 1);
}

// ---------- K4: e_sym[k] = 0.5*(e[win(j,i)] + e[win(i,j)] (or 0)) ----------
__global__ void k_esym(const int* __restrict__ ei, const float* __restrict__ e, int E)
{
    int k = blockIdx.x * blockDim.x + threadIdx.x;
    if (k >= E) return;
    int j = ei[k]     & (NN - 1);
    int i = ei[E + k] & (NN - 1);
    int wf = g_map[j * NN + i] - 1;   // always >= 0 (some edge with this (j,i) wrote it)
    int wr = g_map[i * NN + j];       // 0 if no reverse edge

    const float4* pf = (const float4*)(e + (size_t)wf * 16);
    float4 a0 = pf[0], a1 = pf[1], a2 = pf[2], a3 = pf[3];
    if (wr > 0) {
        const float4* pr = (const float4*)(e + (size_t)(wr - 1) * 16);
        float4 r0 = pr[0], r1 = pr[1], r2 = pr[2], r3 = pr[3];
        a0.x += r0.x; a0.y += r0.y; a0.z += r0.z; a0.w += r0.w;
        a1.x += r1.x; a1.y += r1.y; a1.z += r1.z; a1.w += r1.w;
        a2.x += r2.x; a2.y += r2.y; a2.z += r2.z; a2.w += r2.w;
        a3.x += r3.x; a3.y += r3.y; a3.z += r3.z; a3.w += r3.w;
    }
    a0.x *= 0.5f; a0.y *= 0.5f; a0.z *= 0.5f; a0.w *= 0.5f;
    a1.x *= 0.5f; a1.y *= 0.5f; a1.z *= 0.5f; a1.w *= 0.5f;
    a2.x *= 0.5f; a2.y *= 0.5f; a2.z *= 0.5f; a2.w *= 0.5f;
    a3.x *= 0.5f; a3.y *= 0.5f; a3.z *= 0.5f; a3.w *= 0.5f;
    float4* o = (float4*)(g_esym + (size_t)k * 16);
    o[0] = a0; o[1] = a1; o[2] = a2; o[3] = a3;
}

// ---------- K5: restore g_map zero-invariant for graph replay ----------
__global__ void k_clear(const int* __restrict__ ei, int E)
{
    int k = blockIdx.x * blockDim.x + threadIdx.x;
    if (k >= E) return;
    int j = ei[k]     & (NN - 1);
    int i = ei[E + k] & (NN - 1);
    g_map[j * NN + i] = 0;
}

// ---------- K6: fused edge MLP + bond head (f32x2 packed math) ----------
// Per edge: f = silu(s1[i] + s1[j] + e_sym @ W_bondᵀ + b_bond); bonds = f @ W_bondsᵀ + b_bonds
// Block = 256 threads (8 warps), 256 edges/block. Warp handles 4 edges at a time,
// each lane owns 8 channels (c0 = lane*8), pairs packed for fma.rn.f32x2.
__global__ __launch_bounds__(256) void k_edge(
    const int* __restrict__ ei,
    const float* __restrict__ Wbond,   // [256][16]
    const float* __restrict__ bbond,   // [256]
    const float* __restrict__ Wbonds,  // [5][256]
    const float* __restrict__ bbonds,  // [5]
    float* __restrict__ out, int E)
{
    __shared__ float sWt[16][256];   // W_bondᵀ: [d][c]
    __shared__ float sEs[16][256];   // e_sym tile transposed: [d][edge_local]
    __shared__ float sWb[5][256];    // W_bonds
    __shared__ float sBias[256];     // b_bond
    __shared__ float sBb[8];         // b_bonds
    __shared__ int   sI[256], sJ[256];

    const int tid = threadIdx.x;
    const int eb = blockIdx.x * 256;

    // Stage weights (once per block)
    #pragma unroll
    for (int l = 0; l < 16; l++) {
        int idx = tid + l * 256;             // 4096 = 256*16
        sWt[idx & 15][idx >> 4] = Wbond[idx];
    }
    #pragma unroll
    for (int l = 0; l < 5; l++) sWb[l][tid] = Wbonds[l * 256 + tid];
    sBias[tid] = bbond[tid];
    if (tid < 5) sBb[tid] = bbonds[tid];

    // Stage this tile's edges + esym (transposed)
    {
        int ke = eb + tid;
        if (ke < E) {
            sJ[tid] = ei[ke]     & (NN - 1);
            sI[tid] = ei[E + ke] & (NN - 1);
            const float4* p = (const float4*)(g_esym + (size_t)ke * 16);
            float4 v0 = p[0], v1 = p[1], v2 = p[2], v3 = p[3];
            sEs[ 0][tid] = v0.x; sEs[ 1][tid] = v0.y; sEs[ 2][tid] = v0.z; sEs[ 3][tid] = v0.w;
            sEs[ 4][tid] = v1.x; sEs[ 5][tid] = v1.y; sEs[ 6][tid] = v1.z; sEs[ 7][tid] = v1.w;
            sEs[ 8][tid] = v2.x; sEs[ 9][tid] = v2.y; sEs[10][tid] = v2.z; sEs[11][tid] = v2.w;
            sEs[12][tid] = v3.x; sEs[13][tid] = v3.y; sEs[14][tid] = v3.z; sEs[15][tid] = v3.w;
        } else {
            sJ[tid] = 0; sI[tid] = 0;
            #pragma unroll
            for (int d = 0; d < 16; d++) sEs[d][tid] = 0.f;
        }
    }
    __syncthreads();

    const int lane = tid & 31, wid = tid >> 5;
    const int c0 = lane * 8;

    // Per-lane constant preloads
    unsigned long long bias2[4];
    {
        float4 b0 = *(const float4*)&sBias[c0];
        float4 b1 = *(const float4*)&sBias[c0 + 4];
        bias2[0] = pk2(b0.x, b0.y); bias2[1] = pk2(b0.z, b0.w);
        bias2[2] = pk2(b1.x, b1.y); bias2[3] = pk2(b1.z, b1.w);
    }
    const float bb0 = sBb[0], bb1 = sBb[1], bb2 = sBb[2], bb3 = sBb[3], bb4 = sBb[4];

    for (int it = 0; it < 8; it++) {
        const int e0 = wid * 32 + it * 4;   // local index of first of 4 edges

        // 1) Issue s1 gathers early (L2-resident rows; latency covered by matvec)
        ulonglong2 si[4][2], sj[4][2];
        #pragma unroll
        for (int e = 0; e < 4; e++) {
            int gi = sI[e0 + e], gj = sJ[e0 + e];
            const ulonglong2* pi = (const ulonglong2*)(g_s1 + (size_t)gi * 256 + c0);
            const ulonglong2* pj = (const ulonglong2*)(g_s1 + (size_t)gj * 256 + c0);
            si[e][0] = pi[0]; si[e][1] = pi[1];
            sj[e][0] = pj[0]; sj[e][1] = pj[1];
        }

        // 2) matvec g = b_bond + e_sym @ W_bondᵀ  (packed f32x2)
        unsigned long long g2[4][4];
        #pragma unroll
        for (int e = 0; e < 4; e++) {
            g2[e][0] = bias2[0]; g2[e][1] = bias2[1];
            g2[e][2] = bias2[2]; g2[e][3] = bias2[3];
        }
        #pragma unroll
        for (int k = 0; k < 16; k++) {
            float4 w0 = *(const float4*)&sWt[k][c0];
            float4 w1 = *(const float4*)&sWt[k][c0 + 4];
            unsigned long long B0 = pk2(w0.x, w0.y), B1 = pk2(w0.z, w0.w);
            unsigned long long B2 = pk2(w1.x, w1.y), B3 = pk2(w1.z, w1.w);
            float4 av = *(const float4*)&sEs[k][e0];   // broadcast: 4 edges' e_sym[k]
            float as[4] = {av.x, av.y, av.z, av.w};
            #pragma unroll
            for (int e = 0; e < 4; e++) {
                unsigned long long A = dup2(as[e]);
                fma2(g2[e][0], A, B0); fma2(g2[e][1], A, B1);
                fma2(g2[e][2], A, B2); fma2(g2[e][3], A, B3);
            }
        }

        // 3) add gathers, silu, repack (result reused as f)
        #pragma unroll
        for (int e = 0; e < 4; e++) {
            g2[e][0] = add2(g2[e][0], add2(si[e][0].x, sj[e][0].x));
            g2[e][1] = add2(g2[e][1], add2(si[e][0].y, sj[e][0].y));
            g2[e][2] = add2(g2[e][2], add2(si[e][1].x, sj[e][1].x));
            g2[e][3] = add2(g2[e][3], add2(si[e][1].y, sj[e][1].y));
            #pragma unroll
            for (int p = 0; p < 4; p++) {
                float x0, x1; up2(x0, x1, g2[e][p]);
                g2[e][p] = pk2(silu_f(x0), silu_f(x1));
            }
        }

        // 4) bond head partials (packed)
        unsigned long long bq[4][5];
        #pragma unroll
        for (int e = 0; e < 4; e++)
            #pragma unroll
            for (int b = 0; b < 5; b++) bq[e][b] = 0ull;
        #pragma unroll
        for (int b = 0; b < 5; b++) {
            float4 w0 = *(const float4*)&sWb[b][c0];
            float4 w1 = *(const float4*)&sWb[b][c0 + 4];
            unsigned long long W0 = pk2(w0.x, w0.y), W1 = pk2(w0.z, w0.w);
            unsigned long long W2 = pk2(w1.x, w1.y), W3 = pk2(w1.z, w1.w);
            #pragma unroll
            for (int e = 0; e < 4; e++) {
                fma2(bq[e][b], g2[e][0], W0);
                fma2(bq[e][b], g2[e][1], W1);
                fma2(bq[e][b], g2[e][2], W2);
                fma2(bq[e][b], g2[e][3], W3);
            }
        }

        // 5) horizontal + warp butterfly reduction
        float v[4][5];
        #pragma unroll
        for (int e = 0; e < 4; e++)
            #pragma unroll
            for (int b = 0; b < 5; b++) {
                float lo, hi; up2(lo, hi, bq[e][b]);
                float t = lo + hi;
                t += __shfl_xor_sync(0xffffffffu, t, 16);
                t += __shfl_xor_sync(0xffffffffu, t, 8);
                t += __shfl_xor_sync(0xffffffffu, t, 4);
                t += __shfl_xor_sync(0xffffffffu, t, 2);
                t += __shfl_xor_sync(0xffffffffu, t, 1);
                v[e][b] = t;
            }

        if (lane == 0 && eb + e0 < E) {
            float* o = out + BOND_OFF + (size_t)(eb + e0) * NBT;  // 20 consecutive floats, 16B-aligned
            float4 f0 = make_float4(v[0][0] + bb0, v[0][1] + bb1, v[0][2] + bb2, v[0][3] + bb3);
            float4 f1 = make_float4(v[0][4] + bb4, v[1][0] + bb0, v[1][1] + bb1, v[1][2] + bb2);
            float4 f2 = make_float4(v[1][3] + bb3, v[1][4] + bb4, v[2][0] + bb0, v[2][1] + bb1);
            float4 f3 = make_float4(v[2][2] + bb2, v[2][3] + bb3, v[2][4] + bb4, v[3][0] + bb0);
            float4 f4 = make_float4(v[3][1] + bb1, v[3][2] + bb2, v[3][3] + bb3, v[3][4] + bb4);
            *(float4*)(o +  0) = f0;
            *(float4*)(o +  4) = f1;
            *(float4*)(o +  8) = f2;
            *(float4*)(o + 12) = f3;
            *(float4*)(o + 16) = f4;
        }
    }
}

extern "C" void kernel_launch(void* const* d_in, const int* in_sizes, int n_in,
                              void* d_out, int out_size)
{
    const float* s      = (const float*)d_in[0];
    const float* e      = (const float*)d_in[1];
    // d_in[2] = batch (unused; int32 after JAX x64 demotion)
    const int*   ei     = (const int*)d_in[3];   // edge_index: int32 (JAX demotes int64)
    const float* Wsh    = (const float*)d_in[4];
    const float* bsh    = (const float*)d_in[5];
    const float* Wbond  = (const float*)d_in[6];
    const float* bbond  = (const float*)d_in[7];
    const float* Wbonds = (const float*)d_in[8];
    const float* bbonds = (const float*)d_in[9];
    const float* Watoms = (const float*)d_in[10];
    const float* batoms = (const float*)d_in[11];
    float* out = (float*)d_out;

    // E from e's element count (E*16 floats) — robust to edge_index dtype reporting.
    const int E = in_sizes[1] / EDIM;   // 262144

    // Node path
    k_gemm_silu<<<dim3(4, 32), 256>>>(s, Wsh, bsh);
    k_gemm_atoms<<<dim3(3, 32), 256>>>(Watoms, batoms, out);

    // Edge path: build last-write-wins map, symmetrize, restore map invariant
    int nb = (E + 255) / 256;
    k_scatter<<<nb, 256>>>(ei, E);
    k_esym<<<nb, 256>>>(ei, e, E);
    k_clear<<<nb, 256>>>(ei, E);

    // Fused edge MLP + bond head
    k_edge<<<(E + 255) / 256, 256>>>(ei, Wbond, bbond, Wbonds, bbonds, out, E);
}